// round 5
// baseline (speedup 1.0000x reference)
#include <cuda_runtime.h>

#define BATCH 2
#define NSEQ  2048
#define DIM   1024
#define NH    16
#define HD    64
#define BH    (BATCH * NH)
#define NOUT  3072   // 3 * NH * HD

// Scratch for q/k/v in [b, h, n, d] layout (static device arrays — no allocations).
__device__ float g_q[(size_t)BH * NSEQ * HD];
__device__ float g_k[(size_t)BH * NSEQ * HD];
__device__ float g_v[(size_t)BH * NSEQ * HD];

// ---- packed f32x2 helpers (Blackwell dual-fp32 path) -----------------------
typedef unsigned long long u64;

__device__ __forceinline__ u64 pack2(float x, float y) {
    u64 r; asm("mov.b64 %0, {%1, %2};" : "=l"(r) : "f"(x), "f"(y)); return r;
}
__device__ __forceinline__ void unpack2(u64 v, float& x, float& y) {
    asm("mov.b64 {%0, %1}, %2;" : "=f"(x), "=f"(y) : "l"(v));
}
__device__ __forceinline__ void fma2(u64& acc, u64 a, u64 b) {
    asm("fma.rn.f32x2 %0, %1, %2, %0;" : "+l"(acc) : "l"(a), "l"(b));
}
__device__ __forceinline__ void mul2(u64& d, u64 a, u64 b) {
    asm("mul.rn.f32x2 %0, %1, %2;" : "=l"(d) : "l"(a), "l"(b));
}

// Column bit-permutation for 64-wide b-operand tiles:
// perm(c) = (c&4)<<3 | ((c>>3)&7)<<2 | (c&3).
// Lane tx's 8 columns (c = 8*tx + u) land at slots tx and 8+tx (16B units):
// 8 lanes -> 8 distinct slots mod 8 -> conflict-free LDS.128 b-loads.
__device__ __forceinline__ int perm64(int c) {
    return ((c & 4) << 3) | (((c >> 3) & 7) << 2) | (c & 3);
}

// ---------------------------------------------------------------------------
// Kernel 1: QKV GEMM. C[4096, 3072] = X[4096, 1024] @ W[1024, 3072]
// 128x128 tile, BK=8, 256 threads, 8x8 per-thread micro-tile, f32x2 FMA,
// double-buffered smem (one barrier per k-step).
// As pitch 132 -> conflict-free transpose stores + broadcast a-loads.
// Bs uses a 128-wide column permutation for conflict-free b-loads.
// ---------------------------------------------------------------------------
__global__ __launch_bounds__(256) void qkv_gemm_kernel(
    const float* __restrict__ X, const float* __restrict__ W)
{
    __shared__ float As[2][8][132];
    __shared__ float Bs[2][8][128];

    const int tid = threadIdx.x;
    const int tx = tid & 15;            // col group (8 cols)
    const int ty = tid >> 4;            // row group (8 rows)
    const int rowBase = blockIdx.y << 7;
    const int colBase = blockIdx.x << 7;

    u64 acc[8][4];                      // rows x col-pairs
#pragma unroll
    for (int i = 0; i < 8; i++)
#pragma unroll
        for (int j = 0; j < 4; j++) acc[i][j] = 0ULL;

    const int ar  = tid >> 1;           // 0..127 : A row within tile
    const int akq = (tid & 1) << 2;     // 0,4    : A k-quad
    const int bk  = tid >> 5;           // 0..7   : B k row
    const int bc  = (tid & 31) << 2;    // B col quad
    // 128-wide perm: p(c) = (c&4)<<4 | ((c>>3)&15)<<2 | (c&3); bc has lo2 = 0.
    const int bcp = ((bc & 4) << 4) | (((bc >> 3) & 15) << 2);

    const float* Xp = &X[(size_t)(rowBase + ar) * DIM + akq];
    const float* Wp = &W[(size_t)bk * NOUT + colBase + bc];

    // Prologue
    {
        float4 a = *(const float4*)&Xp[0];
        float4 b = *(const float4*)&Wp[0];
        *(float4*)&Bs[0][bk][bcp] = b;
        As[0][akq + 0][ar] = a.x;
        As[0][akq + 1][ar] = a.y;
        As[0][akq + 2][ar] = a.z;
        As[0][akq + 3][ar] = a.w;
    }
    __syncthreads();

    int buf = 0;
    for (int k0 = 0; k0 < DIM; k0 += 8) {
        const bool has_next = (k0 + 8 < DIM);
        float4 an, bn;
        if (has_next) {
            an = *(const float4*)&Xp[k0 + 8];
            bn = *(const float4*)&Wp[(size_t)(k0 + 8) * NOUT];
        }

#pragma unroll
        for (int kk = 0; kk < 8; kk++) {
            float4 a0 = *(const float4*)&As[buf][kk][ty << 3];
            float4 a1 = *(const float4*)&As[buf][kk][(ty << 3) + 4];
            float4 b0 = *(const float4*)&Bs[buf][kk][tx << 2];        // cols 8tx..+3
            float4 b1 = *(const float4*)&Bs[buf][kk][64 + (tx << 2)]; // cols 8tx+4..+7
            u64 bp[4] = { pack2(b0.x, b0.y), pack2(b0.z, b0.w),
                          pack2(b1.x, b1.y), pack2(b1.z, b1.w) };
            float av[8] = { a0.x, a0.y, a0.z, a0.w, a1.x, a1.y, a1.z, a1.w };
#pragma unroll
            for (int i = 0; i < 8; i++) {
                u64 ad = pack2(av[i], av[i]);
#pragma unroll
                for (int j = 0; j < 4; j++) fma2(acc[i][j], ad, bp[j]);
            }
        }

        if (has_next) {
            const int nb = buf ^ 1;
            *(float4*)&Bs[nb][bk][bcp] = bn;
            As[nb][akq + 0][ar] = an.x;
            As[nb][akq + 1][ar] = an.y;
            As[nb][akq + 2][ar] = an.z;
            As[nb][akq + 3][ar] = an.w;
            __syncthreads();
            buf = nb;
        }
    }

    // Epilogue: scatter into q/k/v with [b,h,n,d] layout. The thread's 8 cols
    // lie entirely within one (section, head) block.
    const int col0 = colBase + (tx << 3);
    const int sec  = col0 >> 10;             // 0=q 1=k 2=v
    const int cc   = col0 & 1023;
    const int h    = cc >> 6;
    const int d0   = cc & 63;
    float* dst = (sec == 0) ? g_q : ((sec == 1) ? g_k : g_v);

#pragma unroll
    for (int i = 0; i < 8; i++) {
        const int row = rowBase + (ty << 3) + i;
        const int b = row >> 11;
        const int n = row & (NSEQ - 1);
        float v[8];
#pragma unroll
        for (int j = 0; j < 4; j++) unpack2(acc[i][j], v[2 * j], v[2 * j + 1]);
        float* p = &dst[(((size_t)(b * NH + h) * NSEQ) + n) * HD + d0];
        *(float4*)&p[0] = make_float4(v[0], v[1], v[2], v[3]);
        *(float4*)&p[4] = make_float4(v[4], v[5], v[6], v[7]);
    }
}

// ---------------------------------------------------------------------------
// Kernel 2: flash attention per (b,h). Br=256, Bc=64, 256 threads (32ty x 8tx),
// 8x8 per-thread micro-tiles for BOTH S = Q K^T and O += P V (f32x2 FMA).
// Online softmax: per-row (m,l) replicated across the 8 tx lanes (shfl w=8).
// Conflict-free smem layouts:
//   Qt [64][256]  Q^T: col = r ^ ((d>>2)<<3)       (a-loads broadcast)
//   Kt [64][64]   K^T: col = perm64(r) ^ ((d>>2&7)<<2)  (b-loads conflict-free)
//   Vs [64][64]   V:   col = perm64(d)             (b-loads conflict-free)
//   Pt [64][256]  P^T: col = r ^ ((c>>3&7)<<2)     (stores + a-loads conflict-free)
// 160 KB dynamic smem, 1 CTA/SM.
// ---------------------------------------------------------------------------
#define ATTN_SMEM_FLOATS (64 * 256 + 64 * 64 + 64 * 64 + 64 * 256)
#define ATTN_SMEM_BYTES  (ATTN_SMEM_FLOATS * 4)

__global__ __launch_bounds__(256, 1) void attn_kernel(float* __restrict__ out)
{
    extern __shared__ float sm[];
    float* Qt = sm;                    // [64][256]
    float* Kt = sm + 64 * 256;         // [64][64]
    float* Vs = Kt + 64 * 64;          // [64][64]
    float* Pt = Vs + 64 * 64;          // [64][256]

    const int tid = threadIdx.x;
    const int tx = tid & 7;            // 8 col groups
    const int ty = tid >> 3;           // 32 row groups
    const int bh = blockIdx.y;
    const int q0 = blockIdx.x << 8;    // 256-row q tile

    const float* qp = g_q + ((size_t)bh * NSEQ + q0) * HD;
    const float* kp = g_k + (size_t)bh * NSEQ * HD;
    const float* vp = g_v + (size_t)bh * NSEQ * HD;

    const float scale = 0.125f;        // 1/sqrt(64)

    // Load Q tile (256x64) transposed + swizzled, pre-scaled.
#pragma unroll
    for (int it = 0; it < 16; it++) {
        const int lin = tid + (it << 8);       // 0..4095 float4 slots
        const int r  = lin >> 4;               // 0..255
        const int d0 = (lin & 15) << 2;        // 0..60
        float4 v = *(const float4*)&qp[r * HD + d0];
        const int c = r ^ ((d0 >> 2) << 3);
        Qt[(d0 + 0) * 256 + c] = v.x * scale;
        Qt[(d0 + 1) * 256 + c] = v.y * scale;
        Qt[(d0 + 2) * 256 + c] = v.z * scale;
        Qt[(d0 + 3) * 256 + c] = v.w * scale;
    }

    float m[8], l[8];
    u64 o2[8][4];
#pragma unroll
    for (int i = 0; i < 8; i++) {
        m[i] = -1e30f;
        l[i] = 0.f;
#pragma unroll
        for (int j = 0; j < 4; j++) o2[i][j] = 0ULL;
    }

    for (int t = 0; t < NSEQ / 64; t++) {
        __syncthreads();   // prev tile's reads of Kt/Vs/Pt complete

        const float* kt = kp + (size_t)t * 64 * HD;
        const float* vt = vp + (size_t)t * 64 * HD;
#pragma unroll
        for (int it = 0; it < 4; it++) {
            const int lin = tid + (it << 8);   // 0..1023
            const int r  = lin >> 4;           // 0..63
            const int d0 = (lin & 15) << 2;
            float4 kv = *(const float4*)&kt[r * HD + d0];
            const int kc = perm64(r) ^ (((d0 >> 2) & 7) << 2);  // row-xor: 2-way stores
            Kt[(d0 + 0) * 64 + kc] = kv.x;
            Kt[(d0 + 1) * 64 + kc] = kv.y;
            Kt[(d0 + 2) * 64 + kc] = kv.z;
            Kt[(d0 + 3) * 64 + kc] = kv.w;
            const int pd = ((d0 & 4) << 3) | ((d0 >> 3) << 2);  // perm64(d0), lo2=0
            *(float4*)&Vs[r * 64 + pd] = *(const float4*)&vt[r * HD + d0];
        }
        __syncthreads();

        // --- S = (Q*scale) K^T : rows ty*8+i, cols tx*8+j ---
        u64 s2[8][4];
#pragma unroll
        for (int i = 0; i < 8; i++)
#pragma unroll
            for (int j = 0; j < 4; j++) s2[i][j] = 0ULL;

#pragma unroll 8
        for (int dd = 0; dd < 64; dd++) {
            const int qb = (ty << 3) ^ ((dd >> 2) << 3);
            const int kb = (tx << 2) ^ (((dd >> 2) & 7) << 2);
            float4 a0 = *(const float4*)&Qt[dd * 256 + qb];
            float4 a1 = *(const float4*)&Qt[dd * 256 + qb + 4];
            float4 b0 = *(const float4*)&Kt[dd * 64 + kb];        // cols 8tx..+3
            float4 b1 = *(const float4*)&Kt[dd * 64 + 32 + kb];   // cols 8tx+4..+7
            u64 bp[4] = { pack2(b0.x, b0.y), pack2(b0.z, b0.w),
                          pack2(b1.x, b1.y), pack2(b1.z, b1.w) };
            float av[8] = { a0.x, a0.y, a0.z, a0.w, a1.x, a1.y, a1.z, a1.w };
#pragma unroll
            for (int i = 0; i < 8; i++) {
                u64 ad = pack2(av[i], av[i]);
#pragma unroll
                for (int j = 0; j < 4; j++) fma2(s2[i][j], ad, bp[j]);
            }
        }

        // --- online softmax (rows ty*8+i; reduce over 8 tx lanes) ---
        float p[8][8];
#pragma unroll
        for (int i = 0; i < 8; i++) {
#pragma unroll
            for (int j = 0; j < 4; j++) unpack2(s2[i][j], p[i][2 * j], p[i][2 * j + 1]);

            float rm = p[i][0];
#pragma unroll
            for (int j = 1; j < 8; j++) rm = fmaxf(rm, p[i][j]);
#pragma unroll
            for (int off = 4; off; off >>= 1)
                rm = fmaxf(rm, __shfl_xor_sync(0xffffffffu, rm, off, 8));

            const float mn = fmaxf(m[i], rm);
            const float al = __expf(m[i] - mn);
            float rs = 0.f;
#pragma unroll
            for (int j = 0; j < 8; j++) {
                p[i][j] = __expf(p[i][j] - mn);
                rs += p[i][j];
            }
#pragma unroll
            for (int off = 4; off; off >>= 1)
                rs += __shfl_xor_sync(0xffffffffu, rs, off, 8);

            l[i] = l[i] * al + rs;
            m[i] = mn;
            u64 alp = pack2(al, al);
#pragma unroll
            for (int j = 0; j < 4; j++) mul2(o2[i][j], o2[i][j], alp);
        }

        // --- stage P^T: Pt[c][r ^ ((c>>3&7)<<2)], c = tx*8+jj ---
        {
            const int swp = tx << 2;                    // (c>>3)&7 == tx
            const int pb0 = (ty << 3) ^ swp;
            const int pb1 = ((ty << 3) + 4) ^ swp;
#pragma unroll
            for (int jj = 0; jj < 8; jj++) {
                float* pp = &Pt[((tx << 3) + jj) * 256];
                *(float4*)&pp[pb0] =
                    make_float4(p[0][jj], p[1][jj], p[2][jj], p[3][jj]);
                *(float4*)&pp[pb1] =
                    make_float4(p[4][jj], p[5][jj], p[6][jj], p[7][jj]);
            }
        }
        __syncthreads();

        // --- O += P V : rows ty*8+i, d cols tx*8+j ---
#pragma unroll 8
        for (int cv = 0; cv < 64; cv++) {
            const int swv = ((cv >> 3) & 7) << 2;
            float4 a0 = *(const float4*)&Pt[cv * 256 + ((ty << 3) ^ swv)];
            float4 a1 = *(const float4*)&Pt[cv * 256 + (((ty << 3) + 4) ^ swv)];
            float4 b0 = *(const float4*)&Vs[cv * 64 + (tx << 2)];       // d 8tx..+3
            float4 b1 = *(const float4*)&Vs[cv * 64 + 32 + (tx << 2)];  // d 8tx+4..+7
            u64 bp[4] = { pack2(b0.x, b0.y), pack2(b0.z, b0.w),
                          pack2(b1.x, b1.y), pack2(b1.z, b1.w) };
            float av[8] = { a0.x, a0.y, a0.z, a0.w, a1.x, a1.y, a1.z, a1.w };
#pragma unroll
            for (int i = 0; i < 8; i++) {
                u64 ad = pack2(av[i], av[i]);
#pragma unroll
                for (int j = 0; j < 4; j++) fma2(o2[i][j], ad, bp[j]);
            }
        }
    }

    // Epilogue
    float* op = out + ((size_t)bh * NSEQ + q0) * HD;
#pragma unroll
    for (int i = 0; i < 8; i++) {
        const float inv = 1.f / l[i];
        const int r = (ty << 3) + i;
        float v[8];
#pragma unroll
        for (int j = 0; j < 4; j++) unpack2(o2[i][j], v[2 * j], v[2 * j + 1]);
        float* pdst = &op[r * HD + (tx << 3)];
        *(float4*)&pdst[0] = make_float4(v[0] * inv, v[1] * inv, v[2] * inv, v[3] * inv);
        *(float4*)&pdst[4] = make_float4(v[4] * inv, v[5] * inv, v[6] * inv, v[7] * inv);
    }
}

// ---------------------------------------------------------------------------
extern "C" void kernel_launch(void* const* d_in, const int* in_sizes, int n_in,
                              void* d_out, int out_size)
{
    const float* x = (const float*)d_in[0];   // [2, 2048, 1024]
    const float* w = (const float*)d_in[1];   // [1024, 3072]
    float* out = (float*)d_out;               // [2, 16, 2048, 64]

    (void)in_sizes; (void)n_in; (void)out_size;

    cudaFuncSetAttribute(attn_kernel, cudaFuncAttributeMaxDynamicSharedMemorySize,
                         ATTN_SMEM_BYTES);

    qkv_gemm_kernel<<<dim3(NOUT / 128, (BATCH * NSEQ) / 128), 256>>>(x, w);
    attn_kernel<<<dim3(NSEQ / 256, BH), 256, ATTN_SMEM_BYTES>>>(out);
}

// round 9
// speedup vs baseline: 1.4770x; 1.4770x over previous
#include <cuda_runtime.h>

#define BATCH 2
#define NSEQ  2048
#define DIM   1024
#define NH    16
#define HD    64
#define BH    (BATCH * NH)
#define NOUT  3072   // 3 * NH * HD

// Scratch for q/k/v in [b, h, n, d] layout (static device arrays — no allocations).
__device__ float g_q[(size_t)BH * NSEQ * HD];
__device__ float g_k[(size_t)BH * NSEQ * HD];
__device__ float g_v[(size_t)BH * NSEQ * HD];

// ---- packed f32x2 helpers (Blackwell dual-fp32 path) -----------------------
typedef unsigned long long u64;

__device__ __forceinline__ u64 pack2(float x, float y) {
    u64 r; asm("mov.b64 %0, {%1, %2};" : "=l"(r) : "f"(x), "f"(y)); return r;
}
__device__ __forceinline__ void unpack2(u64 v, float& x, float& y) {
    asm("mov.b64 {%0, %1}, %2;" : "=f"(x), "=f"(y) : "l"(v));
}
__device__ __forceinline__ void fma2(u64& acc, u64 a, u64 b) {
    asm("fma.rn.f32x2 %0, %1, %2, %0;" : "+l"(acc) : "l"(a), "l"(b));
}
__device__ __forceinline__ void mul2(u64& d, u64 a, u64 b) {
    asm("mul.rn.f32x2 %0, %1, %2;" : "=l"(d) : "l"(a), "l"(b));
}

// Column bit-permutation for 64-wide b-operand tiles:
// perm64(c) = (c&4)<<3 | ((c>>3)&7)<<2 | (c&3).
// Lane tx's 8 columns (c = 8*tx+u) land at 16B-slots tx and 8+tx:
// 8 lanes -> slots distinct mod 8 -> conflict-free LDS.128 b-loads.
__device__ __forceinline__ int perm64(int c) {
    return ((c & 4) << 3) | (((c >> 3) & 7) << 2) | (c & 3);
}

// ---------------------------------------------------------------------------
// Kernel 1: QKV GEMM. C[4096, 3072] = X[4096, 1024] @ W[1024, 3072]
// 64x128 tile, BK=16, 256 threads (16 ty x 16 tx), 4x8 per-thread micro-tile,
// f32x2 FMA, double-buffered smem, 2 CTAs/SM.
// As pitch 68 (16B-aligned rows, stores conflict-free-ish, a-loads broadcast).
// Bs 128-wide column perm: phys(c) = (c&4)<<4 | ((c>>3)&15)<<2 | (c&3).
// ---------------------------------------------------------------------------
__global__ __launch_bounds__(256, 2) void qkv_gemm_kernel(
    const float* __restrict__ X, const float* __restrict__ W)
{
    __shared__ float As[2][16][68];
    __shared__ float Bs[2][16][128];

    const int tid = threadIdx.x;
    const int tx = tid & 15;            // col group (8 cols)
    const int ty = tid >> 4;            // row group (4 rows)
    const int rowBase = blockIdx.y << 6;
    const int colBase = blockIdx.x << 7;

    u64 acc[4][4];                      // 4 rows x 4 col-pairs
#pragma unroll
    for (int i = 0; i < 4; i++)
#pragma unroll
        for (int j = 0; j < 4; j++) acc[i][j] = 0ULL;

    const int ar  = tid >> 2;           // 0..63 : A row within tile
    const int akq = (tid & 3) << 2;     // 0,4,8,12 : A k-quad
    const int bk  = tid >> 4;           // 0..15 : B k row
    const int bt  = tid & 15;           // B col octet index

    const float* Xp = &X[(size_t)(rowBase + ar) * DIM + akq];
    const float* Wp = &W[(size_t)bk * NOUT + colBase + (bt << 3)];

    // Prologue: k0 = 0 into buffer 0.
    {
        float4 a  = *(const float4*)&Xp[0];
        float4 b0 = *(const float4*)&Wp[0];
        float4 b1 = *(const float4*)&Wp[4];
        *(float4*)&Bs[0][bk][bt << 2]        = b0;   // quad 0 -> slot bt
        *(float4*)&Bs[0][bk][64 + (bt << 2)] = b1;   // quad 1 -> slot 16+bt
        As[0][akq + 0][ar] = a.x;
        As[0][akq + 1][ar] = a.y;
        As[0][akq + 2][ar] = a.z;
        As[0][akq + 3][ar] = a.w;
    }
    __syncthreads();

    int buf = 0;
    for (int k0 = 0; k0 < DIM; k0 += 16) {
        const bool has_next = (k0 + 16 < DIM);
        float4 an, bn0, bn1;
        if (has_next) {
            an  = *(const float4*)&Xp[k0 + 16];
            bn0 = *(const float4*)&Wp[(size_t)(k0 + 16) * NOUT];
            bn1 = *(const float4*)&Wp[(size_t)(k0 + 16) * NOUT + 4];
        }

#pragma unroll
        for (int kk = 0; kk < 16; kk++) {
            float4 av = *(const float4*)&As[buf][kk][ty << 2];
            float4 b0 = *(const float4*)&Bs[buf][kk][tx << 2];        // cols 8tx..+3
            float4 b1 = *(const float4*)&Bs[buf][kk][64 + (tx << 2)]; // cols 8tx+4..+7
            u64 bp[4] = { pack2(b0.x, b0.y), pack2(b0.z, b0.w),
                          pack2(b1.x, b1.y), pack2(b1.z, b1.w) };
            float a_[4] = { av.x, av.y, av.z, av.w };
#pragma unroll
            for (int i = 0; i < 4; i++) {
                u64 ad = pack2(a_[i], a_[i]);
#pragma unroll
                for (int j = 0; j < 4; j++) fma2(acc[i][j], ad, bp[j]);
            }
        }

        if (has_next) {
            const int nb = buf ^ 1;
            *(float4*)&Bs[nb][bk][bt << 2]        = bn0;
            *(float4*)&Bs[nb][bk][64 + (bt << 2)] = bn1;
            As[nb][akq + 0][ar] = an.x;
            As[nb][akq + 1][ar] = an.y;
            As[nb][akq + 2][ar] = an.z;
            As[nb][akq + 3][ar] = an.w;
            __syncthreads();
            buf = nb;
        }
    }

    // Epilogue: scatter into q/k/v with [b,h,n,d] layout. The thread's 8 cols
    // lie entirely within one (section, head) block.
    const int col0 = colBase + (tx << 3);
    const int sec  = col0 >> 10;             // 0=q 1=k 2=v
    const int cc   = col0 & 1023;
    const int h    = cc >> 6;
    const int d0   = cc & 63;
    float* dst = (sec == 0) ? g_q : ((sec == 1) ? g_k : g_v);

#pragma unroll
    for (int i = 0; i < 4; i++) {
        const int row = rowBase + (ty << 2) + i;
        const int b = row >> 11;
        const int n = row & (NSEQ - 1);
        float v[8];
#pragma unroll
        for (int j = 0; j < 4; j++) unpack2(acc[i][j], v[2 * j], v[2 * j + 1]);
        float* p = &dst[(((size_t)(b * NH + h) * NSEQ) + n) * HD + d0];
        *(float4*)&p[0] = make_float4(v[0], v[1], v[2], v[3]);
        *(float4*)&p[4] = make_float4(v[4], v[5], v[6], v[7]);
    }
}

// ---------------------------------------------------------------------------
// Kernel 2: flash attention per (b,h). Br=128, Bc=64, 256 threads (32ty x 8tx),
// 4x8 per-thread micro-tiles for BOTH S = Q K^T and O += P V (f32x2 FMA).
// Online softmax: per-row (m,l) replicated across the 8 tx lanes (shfl w=8).
// Conflict-free smem layouts:
//   Qt [64][128]  Q^T: col = r ^ ((d>>2)<<2)            (a-loads broadcast)
//   Kt [64][64]   K^T: col = perm64(r) ^ ((d>>2&7)<<2)  (b-loads conflict-free)
//   Vs [64][64]   V:   col = perm64(d)                  (b-loads conflict-free)
//   Pt [64][128]  P^T: col = r ^ ((c>>3&7)<<2)          (stores+a-loads optimal)
// 96 KB dynamic smem -> 2 CTAs/SM (16 warps).
// ---------------------------------------------------------------------------
#define ATTN_SMEM_FLOATS (64 * 128 + 64 * 64 + 64 * 64 + 64 * 128)
#define ATTN_SMEM_BYTES  (ATTN_SMEM_FLOATS * 4)

__global__ __launch_bounds__(256, 2) void attn_kernel(float* __restrict__ out)
{
    extern __shared__ float sm[];
    float* Qt = sm;                    // [64][128]
    float* Kt = sm + 64 * 128;         // [64][64]
    float* Vs = Kt + 64 * 64;          // [64][64]
    float* Pt = Vs + 64 * 64;          // [64][128]

    const int tid = threadIdx.x;
    const int tx = tid & 7;            // 8 col groups (8 cols each)
    const int ty = tid >> 3;           // 32 row groups (4 rows each)
    const int bh = blockIdx.y;
    const int q0 = blockIdx.x << 7;    // 128-row q tile

    const float* qp = g_q + ((size_t)bh * NSEQ + q0) * HD;
    const float* kp = g_k + (size_t)bh * NSEQ * HD;
    const float* vp = g_v + (size_t)bh * NSEQ * HD;

    const float scale = 0.125f;        // 1/sqrt(64)

    // Load Q tile (128x64) transposed + swizzled, pre-scaled.
#pragma unroll
    for (int it = 0; it < 8; it++) {
        const int lin = tid + (it << 8);       // 0..2047 float4 slots
        const int r  = lin >> 4;               // 0..127
        const int d0 = (lin & 15) << 2;        // 0..60
        float4 v = *(const float4*)&qp[r * HD + d0];
        const int c = r ^ ((d0 >> 2) << 2);
        Qt[(d0 + 0) * 128 + c] = v.x * scale;
        Qt[(d0 + 1) * 128 + c] = v.y * scale;
        Qt[(d0 + 2) * 128 + c] = v.z * scale;
        Qt[(d0 + 3) * 128 + c] = v.w * scale;
    }

    float m[4], l[4];
    u64 o2[4][4];
#pragma unroll
    for (int i = 0; i < 4; i++) {
        m[i] = -1e30f;
        l[i] = 0.f;
#pragma unroll
        for (int j = 0; j < 4; j++) o2[i][j] = 0ULL;
    }

    for (int t = 0; t < NSEQ / 64; t++) {
        __syncthreads();   // prev tile's reads of Kt/Vs complete

        const float* kt = kp + (size_t)t * 64 * HD;
        const float* vt = vp + (size_t)t * 64 * HD;
#pragma unroll
        for (int it = 0; it < 4; it++) {
            const int lin = tid + (it << 8);   // 0..1023
            const int r  = lin >> 4;           // 0..63
            const int d0 = (lin & 15) << 2;
            float4 kv = *(const float4*)&kt[r * HD + d0];
            const int kc = perm64(r) ^ (((d0 >> 2) & 7) << 2);
            Kt[(d0 + 0) * 64 + kc] = kv.x;
            Kt[(d0 + 1) * 64 + kc] = kv.y;
            Kt[(d0 + 2) * 64 + kc] = kv.z;
            Kt[(d0 + 3) * 64 + kc] = kv.w;
            const int pd = ((d0 & 4) << 3) | ((d0 >> 3) << 2);  // perm64(d0)
            *(float4*)&Vs[r * 64 + pd] = *(const float4*)&vt[r * HD + d0];
        }
        __syncthreads();

        // --- S = (Q*scale) K^T : rows ty*4+i, cols tx*8+j ---
        u64 s2[4][4];
#pragma unroll
        for (int i = 0; i < 4; i++)
#pragma unroll
            for (int j = 0; j < 4; j++) s2[i][j] = 0ULL;

#pragma unroll 8
        for (int dd = 0; dd < 64; dd++) {
            const int qb = (ty << 2) ^ ((dd >> 2) << 2);
            const int kb = (tx << 2) ^ (((dd >> 2) & 7) << 2);
            float4 av = *(const float4*)&Qt[dd * 128 + qb];
            float4 b0 = *(const float4*)&Kt[dd * 64 + kb];        // cols 8tx..+3
            float4 b1 = *(const float4*)&Kt[dd * 64 + 32 + kb];   // cols 8tx+4..+7
            u64 bp[4] = { pack2(b0.x, b0.y), pack2(b0.z, b0.w),
                          pack2(b1.x, b1.y), pack2(b1.z, b1.w) };
            float a_[4] = { av.x, av.y, av.z, av.w };
#pragma unroll
            for (int i = 0; i < 4; i++) {
                u64 ad = pack2(a_[i], a_[i]);
#pragma unroll
                for (int j = 0; j < 4; j++) fma2(s2[i][j], ad, bp[j]);
            }
        }

        // --- online softmax (rows ty*4+i; reduce over 8 tx lanes) ---
        float p[4][8];
#pragma unroll
        for (int i = 0; i < 4; i++) {
#pragma unroll
            for (int j = 0; j < 4; j++) unpack2(s2[i][j], p[i][2 * j], p[i][2 * j + 1]);

            float rm = p[i][0];
#pragma unroll
            for (int j = 1; j < 8; j++) rm = fmaxf(rm, p[i][j]);
#pragma unroll
            for (int off = 4; off; off >>= 1)
                rm = fmaxf(rm, __shfl_xor_sync(0xffffffffu, rm, off, 8));

            const float mn = fmaxf(m[i], rm);
            const float al = __expf(m[i] - mn);
            float rs = 0.f;
#pragma unroll
            for (int j = 0; j < 8; j++) {
                p[i][j] = __expf(p[i][j] - mn);
                rs += p[i][j];
            }
#pragma unroll
            for (int off = 4; off; off >>= 1)
                rs += __shfl_xor_sync(0xffffffffu, rs, off, 8);

            l[i] = l[i] * al + rs;
            m[i] = mn;
            u64 alp = pack2(al, al);
#pragma unroll
            for (int j = 0; j < 4; j++) mul2(o2[i][j], o2[i][j], alp);
        }

        // --- stage P^T: Pt[c][r ^ ((c>>3&7)<<2)], c = tx*8+jj ---
        {
            const int pb = (ty << 2) ^ (tx << 2);   // (c>>3)&7 == tx
#pragma unroll
            for (int jj = 0; jj < 8; jj++) {
                float* pp = &Pt[((tx << 3) + jj) * 128];
                *(float4*)&pp[pb] =
                    make_float4(p[0][jj], p[1][jj], p[2][jj], p[3][jj]);
            }
        }
        __syncthreads();

        // --- O += P V : rows ty*4+i, d cols tx*8+j ---
#pragma unroll 8
        for (int cv = 0; cv < 64; cv++) {
            const int swv = ((cv >> 3) & 7) << 2;
            float4 av = *(const float4*)&Pt[cv * 128 + ((ty << 2) ^ swv)];
            float4 b0 = *(const float4*)&Vs[cv * 64 + (tx << 2)];       // d 8tx..+3
            float4 b1 = *(const float4*)&Vs[cv * 64 + 32 + (tx << 2)];  // d 8tx+4..+7
            u64 bp[4] = { pack2(b0.x, b0.y), pack2(b0.z, b0.w),
                          pack2(b1.x, b1.y), pack2(b1.z, b1.w) };
            float a_[4] = { av.x, av.y, av.z, av.w };
#pragma unroll
            for (int i = 0; i < 4; i++) {
                u64 ad = pack2(a_[i], a_[i]);
#pragma unroll
                for (int j = 0; j < 4; j++) fma2(o2[i][j], ad, bp[j]);
            }
        }
    }

    // Epilogue
    float* op = out + ((size_t)bh * NSEQ + q0) * HD;
#pragma unroll
    for (int i = 0; i < 4; i++) {
        const float inv = 1.f / l[i];
        const int r = (ty << 2) + i;
        float v[8];
#pragma unroll
        for (int j = 0; j < 4; j++) unpack2(o2[i][j], v[2 * j], v[2 * j + 1]);
        float* pdst = &op[r * HD + (tx << 3)];
        *(float4*)&pdst[0] = make_float4(v[0] * inv, v[1] * inv, v[2] * inv, v[3] * inv);
        *(float4*)&pdst[4] = make_float4(v[4] * inv, v[5] * inv, v[6] * inv, v[7] * inv);
    }
}

// ---------------------------------------------------------------------------
extern "C" void kernel_launch(void* const* d_in, const int* in_sizes, int n_in,
                              void* d_out, int out_size)
{
    const float* x = (const float*)d_in[0];   // [2, 2048, 1024]
    const float* w = (const float*)d_in[1];   // [1024, 3072]
    float* out = (float*)d_out;               // [2, 16, 2048, 64]

    (void)in_sizes; (void)n_in; (void)out_size;

    cudaFuncSetAttribute(attn_kernel, cudaFuncAttributeMaxDynamicSharedMemorySize,
                         ATTN_SMEM_BYTES);

    qkv_gemm_kernel<<<dim3(NOUT / 128, (BATCH * NSEQ) / 64), 256>>>(x, w);
    attn_kernel<<<dim3(NSEQ / 128, BH), 256, ATTN_SMEM_BYTES>>>(out);
}

// round 16
// speedup vs baseline: 1.8758x; 1.2700x over previous
#include <cuda_runtime.h>
#include <cuda_bf16.h>

#define BATCH 2
#define NSEQ  2048
#define DIM   1024
#define NH    16
#define HD    64
#define BH    (BATCH * NH)
#define NOUT  3072   // 3 * NH * HD

// Scratch (static device arrays — no allocations).
__device__ float g_q[(size_t)BH * NSEQ * HD];
__device__ float g_k[(size_t)BH * NSEQ * HD];
__device__ float g_v[(size_t)BH * NSEQ * HD];
// bf16 error-compensated split of X and W^T (both k-major).
__device__ __nv_bfloat16 g_xhi[(size_t)4096 * DIM];
__device__ __nv_bfloat16 g_xlo[(size_t)4096 * DIM];
__device__ __nv_bfloat16 g_wthi[(size_t)NOUT * DIM];
__device__ __nv_bfloat16 g_wtlo[(size_t)NOUT * DIM];

// ---- packed f32x2 helpers (attention kernel) -------------------------------
typedef unsigned long long u64;

__device__ __forceinline__ u64 pack2(float x, float y) {
    u64 r; asm("mov.b64 %0, {%1, %2};" : "=l"(r) : "f"(x), "f"(y)); return r;
}
__device__ __forceinline__ void unpack2(u64 v, float& x, float& y) {
    asm("mov.b64 {%0, %1}, %2;" : "=f"(x), "=f"(y) : "l"(v));
}
__device__ __forceinline__ void fma2(u64& acc, u64 a, u64 b) {
    asm("fma.rn.f32x2 %0, %1, %2, %0;" : "+l"(acc) : "l"(a), "l"(b));
}
__device__ __forceinline__ void mul2(u64& d, u64 a, u64 b) {
    asm("mul.rn.f32x2 %0, %1, %2;" : "=l"(d) : "l"(a), "l"(b));
}
__device__ __forceinline__ int perm64(int c) {
    return ((c & 4) << 3) | (((c >> 3) & 7) << 2) | (c & 3);
}

__device__ __forceinline__ unsigned smem_u32(const void* p) {
    unsigned a;
    asm("{ .reg .u64 t; cvta.to.shared.u64 t, %1; cvt.u32.u64 %0, t; }"
        : "=r"(a) : "l"(p));
    return a;
}

// ---- HMMA helpers (sm_80+ PTX; compiles under compute_103) -----------------
__device__ __forceinline__ void ldm_x4(unsigned& r0, unsigned& r1,
                                       unsigned& r2, unsigned& r3, unsigned addr) {
    asm volatile("ldmatrix.sync.aligned.m8n8.x4.shared.b16 {%0,%1,%2,%3}, [%4];"
                 : "=r"(r0), "=r"(r1), "=r"(r2), "=r"(r3) : "r"(addr));
}
__device__ __forceinline__ void mma16816(float* d, const unsigned* a,
                                         const unsigned* b) {
    asm volatile(
        "mma.sync.aligned.m16n8k16.row.col.f32.bf16.bf16.f32 "
        "{%0,%1,%2,%3}, {%4,%5,%6,%7}, {%8,%9}, {%0,%1,%2,%3};"
        : "+f"(d[0]), "+f"(d[1]), "+f"(d[2]), "+f"(d[3])
        : "r"(a[0]), "r"(a[1]), "r"(a[2]), "r"(a[3]), "r"(b[0]), "r"(b[1]));
}

// ---------------------------------------------------------------------------
// Split kernels: X -> Xhi+Xlo (bf16); W -> Wt_hi/Wt_lo (bf16, transposed).
// ---------------------------------------------------------------------------
__global__ void split_x_kernel(const float* __restrict__ X)
{
    const int i = blockIdx.x * 256 + threadIdx.x;     // float4 index
    float4 v = ((const float4*)X)[i];
    const int base = i * 4;
    float f[4] = { v.x, v.y, v.z, v.w };
#pragma unroll
    for (int j = 0; j < 4; j++) {
        __nv_bfloat16 h = __float2bfloat16(f[j]);
        g_xhi[base + j] = h;
        g_xlo[base + j] = __float2bfloat16(f[j] - __bfloat162float(h));
    }
}

__global__ void split_w_kernel(const float* __restrict__ W)
{
    __shared__ float ts[32][33];
    const int n0 = blockIdx.x * 32;
    const int k0 = blockIdx.y * 32;
    const int tx = threadIdx.x;   // 0..31
    const int ty = threadIdx.y;   // 0..7
#pragma unroll
    for (int i = 0; i < 4; i++) {
        const int r = ty * 4 + i;                          // k-local
        ts[r][tx] = W[(size_t)(k0 + r) * NOUT + n0 + tx];
    }
    __syncthreads();
#pragma unroll
    for (int i = 0; i < 4; i++) {
        const int r = ty * 4 + i;                          // n-local
        const float v = ts[tx][r];                         // = W[k0+tx][n0+r]
        __nv_bfloat16 h = __float2bfloat16(v);
        g_wthi[(size_t)(n0 + r) * DIM + k0 + tx] = h;
        g_wtlo[(size_t)(n0 + r) * DIM + k0 + tx] =
            __float2bfloat16(v - __bfloat162float(h));
    }
}

// ---------------------------------------------------------------------------
// QKV GEMM via mma.sync (HMMA bf16): C[4096,3072] = X @ W.
// 128x128 CTA tile, 8 warps (2 M x 4 N), warp tile 64x32, BK=32.
// 3-product compensated accumulate: Ahi*Bhi + Ahi*Blo + Alo*Bhi.
// Smem tiles 128 rows x 32 bf16, pitch 80B (rows -> banks 20r mod 32, the
// 8 consecutive rows of an ldmatrix phase hit 8 distinct banks).
// ---------------------------------------------------------------------------
#define QPITCH 80   // bytes per smem tile row (32 bf16 data + 16B pad)

__global__ __launch_bounds__(256, 2) void qkv_hmma_kernel()
{
    __shared__ __align__(16) char smAhi[128 * QPITCH];
    __shared__ __align__(16) char smAlo[128 * QPITCH];
    __shared__ __align__(16) char smBhi[128 * QPITCH];
    __shared__ __align__(16) char smBlo[128 * QPITCH];

    const int tid  = threadIdx.x;
    const int wid  = tid >> 5;
    const int lane = tid & 31;
    const int wm = wid >> 2;          // 0..1  (64-row slice)
    const int wn = wid & 3;           // 0..3  (32-col slice)
    const int nBase = blockIdx.x << 7;
    const int mBase = blockIdx.y << 7;

    const __nv_bfloat16* gsrc[4] = {
        g_xhi  + (size_t)mBase * DIM,
        g_xlo  + (size_t)mBase * DIM,
        g_wthi + (size_t)nBase * DIM,
        g_wtlo + (size_t)nBase * DIM,
    };
    char* sdst[4] = { smAhi, smAlo, smBhi, smBlo };

    float d[4][4][4];                 // [mi][ni][frag]
#pragma unroll
    for (int mi = 0; mi < 4; mi++)
#pragma unroll
        for (int ni = 0; ni < 4; ni++)
#pragma unroll
            for (int f = 0; f < 4; f++) d[mi][ni][f] = 0.f;

    const unsigned sAhi = smem_u32(smAhi), sAlo = smem_u32(smAlo);
    const unsigned sBhi = smem_u32(smBhi), sBlo = smem_u32(smBlo);

    for (int kc = 0; kc < DIM / 32; kc++) {
        // --- load 4 tiles (128x32 bf16 each): 2 x 16B per thread per tile ---
#pragma unroll
        for (int bufi = 0; bufi < 4; bufi++) {
#pragma unroll
            for (int it = 0; it < 2; it++) {
                const int unit = tid + (it << 8);   // 0..511
                const int row = unit >> 2;
                const int u = unit & 3;
                uint4 v = *(const uint4*)(gsrc[bufi] + (size_t)row * DIM + kc * 32 + u * 8);
                *(uint4*)(sdst[bufi] + row * QPITCH + u * 16) = v;
            }
        }
        __syncthreads();

#pragma unroll
        for (int ksel = 0; ksel < 2; ksel++) {
            // A fragments (hi, lo): 4 m16 tiles each
            unsigned ahi[4][4], alo[4][4];
#pragma unroll
            for (int mi = 0; mi < 4; mi++) {
                const unsigned off =
                    (unsigned)((wm * 64 + mi * 16 + (lane & 15)) * QPITCH +
                               (ksel * 2 + (lane >> 4)) * 16);
                ldm_x4(ahi[mi][0], ahi[mi][1], ahi[mi][2], ahi[mi][3], sAhi + off);
                ldm_x4(alo[mi][0], alo[mi][1], alo[mi][2], alo[mi][3], sAlo + off);
            }
            // B fragments (hi, lo): 4 n8 tiles each (2 ldmatrix.x4)
            unsigned bhi[4][2], blo[4][2];
#pragma unroll
            for (int nj = 0; nj < 2; nj++) {
                const int g = lane >> 3;            // 0..3
                const int r = lane & 7;
                const unsigned off =
                    (unsigned)((wn * 32 + nj * 16 + (g >> 1) * 8 + r) * QPITCH +
                               (ksel * 2 + (g & 1)) * 16);
                unsigned t0, t1, t2, t3;
                ldm_x4(t0, t1, t2, t3, sBhi + off);
                bhi[nj * 2][0] = t0; bhi[nj * 2][1] = t1;
                bhi[nj * 2 + 1][0] = t2; bhi[nj * 2 + 1][1] = t3;
                ldm_x4(t0, t1, t2, t3, sBlo + off);
                blo[nj * 2][0] = t0; blo[nj * 2][1] = t1;
                blo[nj * 2 + 1][0] = t2; blo[nj * 2 + 1][1] = t3;
            }
            // 3 products x 16 tiles
#pragma unroll
            for (int mi = 0; mi < 4; mi++)
#pragma unroll
                for (int ni = 0; ni < 4; ni++) {
                    mma16816(d[mi][ni], ahi[mi], bhi[ni]);
                    mma16816(d[mi][ni], ahi[mi], blo[ni]);
                    mma16816(d[mi][ni], alo[mi], bhi[ni]);
                }
        }
        __syncthreads();
    }

    // --- epilogue: scatter into g_q/g_k/g_v ([b,h,n,d]) ---
    // Warp's 32 cols lie within one 64-wide head.
    const int colW = nBase + wn * 32;
    const int sec = colW >> 10;
    const int h = (colW & 1023) >> 6;
    const int dBase = colW & 63;
    float* dst = (sec == 0) ? g_q : ((sec == 1) ? g_k : g_v);

#pragma unroll
    for (int mi = 0; mi < 4; mi++) {
#pragma unroll
        for (int rr = 0; rr < 2; rr++) {
            const int mg = mBase + wm * 64 + mi * 16 + rr * 8 + (lane >> 2);
            const int b = mg >> 11, n = mg & (NSEQ - 1);
            float* dp = &dst[(((size_t)(b * NH + h) * NSEQ) + n) * HD + dBase];
#pragma unroll
            for (int ni = 0; ni < 4; ni++) {
                const int c = ni * 8 + (lane & 3) * 2;
                *(float2*)&dp[c] = make_float2(d[mi][ni][rr * 2], d[mi][ni][rr * 2 + 1]);
            }
        }
    }
}

// ---------------------------------------------------------------------------
// Kernel 2: flash attention (unchanged from measured 862us version).
// ---------------------------------------------------------------------------
#define ATTN_SMEM_FLOATS (64 * 128 + 64 * 64 + 64 * 64 + 64 * 128)
#define ATTN_SMEM_BYTES  (ATTN_SMEM_FLOATS * 4)

__global__ __launch_bounds__(256, 2) void attn_kernel(float* __restrict__ out)
{
    extern __shared__ float sm[];
    float* Qt = sm;                    // [64][128]
    float* Kt = sm + 64 * 128;         // [64][64]
    float* Vs = Kt + 64 * 64;          // [64][64]
    float* Pt = Vs + 64 * 64;          // [64][128]

    const int tid = threadIdx.x;
    const int tx = tid & 7;
    const int ty = tid >> 3;
    const int bh = blockIdx.y;
    const int q0 = blockIdx.x << 7;

    const float* qp = g_q + ((size_t)bh * NSEQ + q0) * HD;
    const float* kp = g_k + (size_t)bh * NSEQ * HD;
    const float* vp = g_v + (size_t)bh * NSEQ * HD;

    const float scale = 0.125f;

#pragma unroll
    for (int it = 0; it < 8; it++) {
        const int lin = tid + (it << 8);
        const int r  = lin >> 4;
        const int d0 = (lin & 15) << 2;
        float4 v = *(const float4*)&qp[r * HD + d0];
        const int c = r ^ ((d0 >> 2) << 2);
        Qt[(d0 + 0) * 128 + c] = v.x * scale;
        Qt[(d0 + 1) * 128 + c] = v.y * scale;
        Qt[(d0 + 2) * 128 + c] = v.z * scale;
        Qt[(d0 + 3) * 128 + c] = v.w * scale;
    }

    float m[4], l[4];
    u64 o2[4][4];
#pragma unroll
    for (int i = 0; i < 4; i++) {
        m[i] = -1e30f;
        l[i] = 0.f;
#pragma unroll
        for (int j = 0; j < 4; j++) o2[i][j] = 0ULL;
    }

    for (int t = 0; t < NSEQ / 64; t++) {
        __syncthreads();

        const float* kt = kp + (size_t)t * 64 * HD;
        const float* vt = vp + (size_t)t * 64 * HD;
#pragma unroll
        for (int it = 0; it < 4; it++) {
            const int lin = tid + (it << 8);
            const int r  = lin >> 4;
            const int d0 = (lin & 15) << 2;
            float4 kv = *(const float4*)&kt[r * HD + d0];
            const int kc = perm64(r) ^ (((d0 >> 2) & 7) << 2);
            Kt[(d0 + 0) * 64 + kc] = kv.x;
            Kt[(d0 + 1) * 64 + kc] = kv.y;
            Kt[(d0 + 2) * 64 + kc] = kv.z;
            Kt[(d0 + 3) * 64 + kc] = kv.w;
            const int pd = ((d0 & 4) << 3) | ((d0 >> 3) << 2);
            *(float4*)&Vs[r * 64 + pd] = *(const float4*)&vt[r * HD + d0];
        }
        __syncthreads();

        u64 s2[4][4];
#pragma unroll
        for (int i = 0; i < 4; i++)
#pragma unroll
            for (int j = 0; j < 4; j++) s2[i][j] = 0ULL;

#pragma unroll 8
        for (int dd = 0; dd < 64; dd++) {
            const int qb = (ty << 2) ^ ((dd >> 2) << 2);
            const int kb = (tx << 2) ^ (((dd >> 2) & 7) << 2);
            float4 av = *(const float4*)&Qt[dd * 128 + qb];
            float4 b0 = *(const float4*)&Kt[dd * 64 + kb];
            float4 b1 = *(const float4*)&Kt[dd * 64 + 32 + kb];
            u64 bp[4] = { pack2(b0.x, b0.y), pack2(b0.z, b0.w),
                          pack2(b1.x, b1.y), pack2(b1.z, b1.w) };
            float a_[4] = { av.x, av.y, av.z, av.w };
#pragma unroll
            for (int i = 0; i < 4; i++) {
                u64 ad = pack2(a_[i], a_[i]);
#pragma unroll
                for (int j = 0; j < 4; j++) fma2(s2[i][j], ad, bp[j]);
            }
        }

        float p[4][8];
#pragma unroll
        for (int i = 0; i < 4; i++) {
#pragma unroll
            for (int j = 0; j < 4; j++) unpack2(s2[i][j], p[i][2 * j], p[i][2 * j + 1]);

            float rm = p[i][0];
#pragma unroll
            for (int j = 1; j < 8; j++) rm = fmaxf(rm, p[i][j]);
#pragma unroll
            for (int off = 4; off; off >>= 1)
                rm = fmaxf(rm, __shfl_xor_sync(0xffffffffu, rm, off, 8));

            const float mn = fmaxf(m[i], rm);
            const float al = __expf(m[i] - mn);
            float rs = 0.f;
#pragma unroll
            for (int j = 0; j < 8; j++) {
                p[i][j] = __expf(p[i][j] - mn);
                rs += p[i][j];
            }
#pragma unroll
            for (int off = 4; off; off >>= 1)
                rs += __shfl_xor_sync(0xffffffffu, rs, off, 8);

            l[i] = l[i] * al + rs;
            m[i] = mn;
            u64 alp = pack2(al, al);
#pragma unroll
            for (int j = 0; j < 4; j++) mul2(o2[i][j], o2[i][j], alp);
        }

        {
            const int pb = (ty << 2) ^ (tx << 2);
#pragma unroll
            for (int jj = 0; jj < 8; jj++) {
                float* pp = &Pt[((tx << 3) + jj) * 128];
                *(float4*)&pp[pb] =
                    make_float4(p[0][jj], p[1][jj], p[2][jj], p[3][jj]);
            }
        }
        __syncthreads();

#pragma unroll 8
        for (int cv = 0; cv < 64; cv++) {
            const int swv = ((cv >> 3) & 7) << 2;
            float4 av = *(const float4*)&Pt[cv * 128 + ((ty << 2) ^ swv)];
            float4 b0 = *(const float4*)&Vs[cv * 64 + (tx << 2)];
            float4 b1 = *(const float4*)&Vs[cv * 64 + 32 + (tx << 2)];
            u64 bp[4] = { pack2(b0.x, b0.y), pack2(b0.z, b0.w),
                          pack2(b1.x, b1.y), pack2(b1.z, b1.w) };
            float a_[4] = { av.x, av.y, av.z, av.w };
#pragma unroll
            for (int i = 0; i < 4; i++) {
                u64 ad = pack2(a_[i], a_[i]);
#pragma unroll
                for (int j = 0; j < 4; j++) fma2(o2[i][j], ad, bp[j]);
            }
        }
    }

    float* op = out + ((size_t)bh * NSEQ + q0) * HD;
#pragma unroll
    for (int i = 0; i < 4; i++) {
        const float inv = 1.f / l[i];
        const int r = (ty << 2) + i;
        float v[8];
#pragma unroll
        for (int j = 0; j < 4; j++) unpack2(o2[i][j], v[2 * j], v[2 * j + 1]);
        float* pdst = &op[r * HD + (tx << 3)];
        *(float4*)&pdst[0] = make_float4(v[0] * inv, v[1] * inv, v[2] * inv, v[3] * inv);
        *(float4*)&pdst[4] = make_float4(v[4] * inv, v[5] * inv, v[6] * inv, v[7] * inv);
    }
}

// ---------------------------------------------------------------------------
extern "C" void kernel_launch(void* const* d_in, const int* in_sizes, int n_in,
                              void* d_out, int out_size)
{
    const float* x = (const float*)d_in[0];   // [2, 2048, 1024]
    const float* w = (const float*)d_in[1];   // [1024, 3072]
    float* out = (float*)d_out;               // [2, 16, 2048, 64]

    (void)in_sizes; (void)n_in; (void)out_size;

    cudaFuncSetAttribute(attn_kernel, cudaFuncAttributeMaxDynamicSharedMemorySize,
                         ATTN_SMEM_BYTES);

    split_x_kernel<<<4096, 256>>>(x);
    split_w_kernel<<<dim3(NOUT / 32, DIM / 32), dim3(32, 8)>>>(w);
    qkv_hmma_kernel<<<dim3(NOUT / 128, 4096 / 128), 256>>>();
    attn_kernel<<<dim3(NSEQ / 128, BH), 256, ATTN_SMEM_BYTES>>>(out);
}